// round 2
// baseline (speedup 1.0000x reference)
#include <cuda_runtime.h>
#include <stdint.h>

#define BATCH 16
#define H 1024
#define W 1024
#define HW (H*W)
#define NPIX (BATCH*HW)

// ---------------- scratch (static device globals; no allocs) ----------------
__device__ int d_labels[NPIX];
__device__ int d_counts[NPIX];
__device__ unsigned char d_fg[NPIX];
__device__ unsigned long long d_winner[BATCH];

// ---------------- lock-free union-find (Playne-Stepanek style) --------------
// Unions always attach larger index under smaller index, so each component's
// final root is its MINIMUM linear index -> exactly matches the reference's
// min-propagation fixed point (labels + argmax tie-breaking identical).
__device__ __forceinline__ int findRoot(int* L, int x) {
    int p = L[x];
    while (p != x) { x = p; p = L[x]; }
    return x;
}

__device__ __forceinline__ void unite(int* L, int a, int b) {
    a = findRoot(L, a);
    b = findRoot(L, b);
    while (a != b) {
        if (a < b) { int t = a; a = b; b = t; }   // ensure a > b
        int old = atomicMin(&L[a], b);
        if (old == a) a = b;                      // linked successfully
        else a = old;                             // retry with displaced value
    }
}

// ---------------- kernel 1: fg + tile-local CC in shared memory -------------
// Block = 32x32 threads over a 32x32 tile. Local union-find in shared memory,
// then each pixel's global label = global index of its local root (depth-1 trees).
__global__ __launch_bounds__(1024) void k_init_local(const float* __restrict__ x) {
    __shared__ int sl[1024];
    __shared__ unsigned char sf[1024];

    const int tx = threadIdx.x, ty = threadIdx.y;
    const int t = ty * 32 + tx;
    const int b = blockIdx.z;
    const int row = blockIdx.y * 32 + ty;
    const int col = blockIdx.x * 32 + tx;
    const int p = row * W + col;
    const int g = b * HW + p;

    const float* xb = x + (size_t)b * 2 * HW;
    const float v0 = xb[p];
    const float v1 = xb[HW + p];
    const int fg = (v1 > v0) ? 1 : 0;   // argmax over 2 classes, ties -> class 0

    sl[t] = t;
    sf[t] = (unsigned char)fg;
    __syncthreads();

    if (fg) {
        if (tx > 0 && sf[t - 1])            unite(sl, t, t - 1);
        if (ty > 0) {
            if (sf[t - 32])                 unite(sl, t, t - 32);
            if (tx > 0  && sf[t - 33])      unite(sl, t, t - 33);
            if (tx < 31 && sf[t - 31])      unite(sl, t, t - 31);
        }
    }
    __syncthreads();

    int lab;
    if (fg) {
        int r = findRoot(sl, t);
        int rrow = blockIdx.y * 32 + (r >> 5);
        int rcol = blockIdx.x * 32 + (r & 31);
        lab = b * HW + rrow * W + rcol;
    } else {
        lab = g;   // background: self (never merged, never matches winner)
    }
    d_labels[g] = lab;
    d_fg[g] = (unsigned char)fg;
    d_counts[g] = 0;

    if (blockIdx.x == 0 && blockIdx.y == 0 && blockIdx.z == 0 && t < BATCH)
        d_winner[t] = 0ULL;
}

// ---------------- kernel 2: merge across tile borders -----------------------
// For each pixel on a tile top-row: union N, NW, NE. On a tile left-col:
// union W, NW, SW. This covers every cross-tile 8-adjacency exactly once-ish.
__global__ void k_border() {
    const int perB = 2 * 31 * 1024;
    int idx = blockIdx.x * blockDim.x + threadIdx.x;
    if (idx >= BATCH * perB) return;
    const int b = idx / perB;
    int j = idx - b * perB;
    const int base = b * HW;

    if (j < 31 * 1024) {
        // horizontal tile boundary: rows 32,64,...,992
        const int r = 32 * (1 + (j >> 10));
        const int c = j & 1023;
        const int p = base + r * W + c;
        if (!d_fg[p]) return;
        const int up = p - W;
        if (d_fg[up])                 unite(d_labels, p, up);
        if (c > 0     && d_fg[up-1])  unite(d_labels, p, up - 1);
        if (c < W - 1 && d_fg[up+1])  unite(d_labels, p, up + 1);
    } else {
        // vertical tile boundary: cols 32,64,...,992
        j -= 31 * 1024;
        const int c = 32 * (1 + (j >> 10));
        const int r = j & 1023;
        const int p = base + r * W + c;
        if (!d_fg[p]) return;
        const int lf = p - 1;
        if (d_fg[lf])                 unite(d_labels, p, lf);
        if (r > 0     && d_fg[lf-W])  unite(d_labels, p, lf - W);
        if (r < H - 1 && d_fg[lf+W])  unite(d_labels, p, lf + W);
    }
}

// ---------------- kernel 3: flatten + per-block hashed counting -------------
__global__ __launch_bounds__(1024) void k_flatten_count() {
    __shared__ int hkey[256];
    __shared__ int hval[256];
    const int tid = threadIdx.x;
    if (tid < 256) { hkey[tid] = -1; hval[tid] = 0; }
    __syncthreads();

    const int i = blockIdx.x * 1024 + tid;
    const int root = findRoot(d_labels, i);
    d_labels[i] = root;                       // full path compression

    if (d_fg[i]) {
        unsigned h = ((unsigned)root * 2654435761u) >> 24;   // 8-bit hash
        bool done = false;
        #pragma unroll 4
        for (int probe = 0; probe < 256; ++probe) {
            int k = atomicCAS(&hkey[h], -1, root);
            if (k == -1 || k == root) { atomicAdd(&hval[h], 1); done = true; break; }
            h = (h + 1) & 255;
        }
        if (!done) atomicAdd(&d_counts[root], 1);   // overflow fallback
    }
    __syncthreads();

    if (tid < 256 && hkey[tid] >= 0)
        atomicAdd(&d_counts[hkey[tid]], hval[tid]);
}

// ---------------- kernel 4: per-batch argmax of counts ----------------------
// key = (count << 32) | (0xFFFFFFFF - global_root): max count wins, ties
// broken toward the smaller root index (same as jnp.argmax first-max rule).
__global__ void k_argmax() {
    __shared__ unsigned long long smax;
    const int i = blockIdx.x * blockDim.x + threadIdx.x;   // over NPIX/4
    const int base = i * 4;
    int4 c = ((const int4*)d_counts)[i];

    unsigned long long key = 0ULL;
    const int cv[4] = {c.x, c.y, c.z, c.w};
    #pragma unroll
    for (int j = 0; j < 4; ++j) {
        if (cv[j] > 0) {
            unsigned long long k = ((unsigned long long)(unsigned)cv[j] << 32)
                                 | (unsigned long long)(0xFFFFFFFFu - (unsigned)(base + j));
            if (k > key) key = k;
        }
    }
    #pragma unroll
    for (int off = 16; off > 0; off >>= 1) {
        unsigned long long o = __shfl_down_sync(0xFFFFFFFFu, key, off);
        if (o > key) key = o;
    }
    if (threadIdx.x == 0) smax = 0ULL;
    __syncthreads();
    if ((threadIdx.x & 31) == 0 && key) atomicMax(&smax, key);
    __syncthreads();
    if (threadIdx.x == 0 && smax) {
        const int b = base / HW;    // block spans one batch (1024 px | HW)
        atomicMax(&d_winner[b], smax);
    }
}

// ---------------- kernel 5: masked output, vectorized -----------------------
__global__ void k_write(const float* __restrict__ x, float* __restrict__ out) {
    const int i = blockIdx.x * blockDim.x + threadIdx.x;   // over NPIX/4
    const int p4 = i * 4;
    const int b = p4 / HW;
    const int p = p4 - b * HW;

    const unsigned long long wk = d_winner[b];
    // no foreground -> wk==0 -> wroot = -1, matches nothing
    const int wroot = (int)(0xFFFFFFFFu - (unsigned)(wk & 0xFFFFFFFFu));

    const int4 lab = ((const int4*)d_labels)[i];
    const float* xb = x + (size_t)b * 2 * HW;
    const float4 v0 = *(const float4*)(xb + p);
    const float4 v1 = *(const float4*)(xb + HW + p);

    float4 o0, o1;
    o0.x = (lab.x == wroot) ? v0.x : 0.0f;
    o0.y = (lab.y == wroot) ? v0.y : 0.0f;
    o0.z = (lab.z == wroot) ? v0.z : 0.0f;
    o0.w = (lab.w == wroot) ? v0.w : 0.0f;
    o1.x = (lab.x == wroot) ? v1.x : 0.0f;
    o1.y = (lab.y == wroot) ? v1.y : 0.0f;
    o1.z = (lab.z == wroot) ? v1.z : 0.0f;
    o1.w = (lab.w == wroot) ? v1.w : 0.0f;

    float* ob = out + (size_t)b * 2 * HW;
    *(float4*)(ob + p) = o0;
    *(float4*)(ob + HW + p) = o1;
}

// ---------------- launcher --------------------------------------------------
extern "C" void kernel_launch(void* const* d_in, const int* in_sizes, int n_in,
                              void* d_out, int out_size) {
    const float* x = (const float*)d_in[0];
    float* out = (float*)d_out;

    {   // 1. fg + tile-local CC + scratch init
        dim3 blk(32, 32);
        dim3 grd(W / 32, H / 32, BATCH);
        k_init_local<<<grd, blk>>>(x);
    }
    {   // 2. cross-tile border merges
        const int n = BATCH * 2 * 31 * 1024;
        k_border<<<(n + 255) / 256, 256>>>();
    }
    {   // 3. flatten + count
        k_flatten_count<<<NPIX / 1024, 1024>>>();
    }
    {   // 4. per-batch argmax
        k_argmax<<<(NPIX / 4) / 256, 256>>>();
    }
    {   // 5. masked output
        k_write<<<(NPIX / 4) / 256, 256>>>(x, out);
    }
}